// round 11
// baseline (speedup 1.0000x reference)
#include <cuda_runtime.h>
#include <cuda_fp16.h>
#include <stdint.h>

#define Bn 8
#define Ln 2048
#define Dn 64
#define BT 128
#define NT 16
#define NTH 512
#define TILE_ELEMS (BT * Dn)          // 8192
#define TILE_BYTES (TILE_ELEMS * 2)   // 16384

// fp16 scratch: [0]=Q(prescaled by 0.125*log2e), [1]=K, [2]=V; SW128-swizzled tile blobs
__device__ __align__(256) __half g_h[3][Bn * Ln * Dn];

__host__ __device__ __forceinline__ uint32_t sw128(uint32_t x) {
    return x ^ ((x >> 3) & 0x70);
}

// ---------------- smem layout (bytes) ----------------
#define SM_QH 0
#define SM_KV TILE_BYTES                        // 4 ring bufs x {Kh, Vh} = 131072
#define KVBUF(i) (SM_KV + (uint32_t)(i) * 2u * TILE_BYTES)
#define OST 66                                   // padded obuf row stride (floats)
#define OREG (BT * OST * 4)                      // 33792 B per partial-O region
#define SM_OB (SM_KV + 8 * TILE_BYTES)           // 147456: 2 regions
#define SM_LB (SM_OB + 2 * OREG)                 // 215040: 4*128 floats
#define SMEM_TOTAL (SM_LB + 2048)                // 217088

// ---------------- asm helpers (base ISA, compute_103-safe) ----------------
__device__ __forceinline__ uint32_t smem_u32(const void* p) {
    uint32_t a;
    asm("{ .reg .u64 t; cvta.to.shared.u64 t, %1; cvt.u32.u64 %0, t; }" : "=r"(a) : "l"(p));
    return a;
}
#define CP16(dst, src) \
    asm volatile("cp.async.cg.shared.global [%0], [%1], 16;" :: "r"(dst), "l"(src))
#define CPCOMMIT() asm volatile("cp.async.commit_group;" ::: "memory")
#define CPWAIT2()  asm volatile("cp.async.wait_group 2;" ::: "memory")
#define CPWAIT1()  asm volatile("cp.async.wait_group 1;" ::: "memory")
#define CPWAIT0()  asm volatile("cp.async.wait_group 0;" ::: "memory")

__device__ __forceinline__ void ldsm4(uint32_t* r, uint32_t a) {
    asm volatile("ldmatrix.sync.aligned.m8n8.x4.shared.b16 {%0,%1,%2,%3}, [%4];"
                 : "=r"(r[0]), "=r"(r[1]), "=r"(r[2]), "=r"(r[3]) : "r"(a));
}
__device__ __forceinline__ void ldsm4t(uint32_t* r, uint32_t a) {
    asm volatile("ldmatrix.sync.aligned.m8n8.x4.trans.shared.b16 {%0,%1,%2,%3}, [%4];"
                 : "=r"(r[0]), "=r"(r[1]), "=r"(r[2]), "=r"(r[3]) : "r"(a));
}
__device__ __forceinline__ void mma16816(float* c, const uint32_t* a, const uint32_t* b) {
    asm volatile("mma.sync.aligned.m16n8k16.row.col.f32.f16.f16.f32 "
                 "{%0,%1,%2,%3}, {%4,%5,%6,%7}, {%8,%9}, {%0,%1,%2,%3};"
                 : "+f"(c[0]), "+f"(c[1]), "+f"(c[2]), "+f"(c[3])
                 : "r"(a[0]), "r"(a[1]), "r"(a[2]), "r"(a[3]), "r"(b[0]), "r"(b[1]));
}
// pack two fp32 to half2 (bits), then exp2 on both halves in one MUFU op
__device__ __forceinline__ uint32_t pkh2(float lo, float hi) {
    __half2 h = __floats2half2_rn(lo, hi);
    return *reinterpret_cast<uint32_t*>(&h);
}
__device__ __forceinline__ uint32_t ex2h2(uint32_t x) {
    uint32_t r;
    asm("ex2.approx.f16x2 %0, %1;" : "=r"(r) : "r"(x));
    return r;
}

// swizzled address of (row, 16B-chunk) in a 128x64 fp16 tile blob
__device__ __forceinline__ uint32_t taddr(uint32_t base, int row, int ch) {
    return base + ((uint32_t)row << 7) + (uint32_t)((ch ^ (row & 7)) << 4);
}
// pattern P1 (A-frag / V trans-frag): groups {r0,c0},{r0+8,c0},{r0,c0+1},{r0+8,c0+1}
__device__ __forceinline__ uint32_t addrP1(uint32_t base, int r0, int c0, int lane) {
    int grp = lane >> 3;
    return taddr(base, r0 + (grp & 1) * 8 + (lane & 7), c0 + (grp >> 1));
}
// pattern P2 (K B-frag): groups {r0,c0},{r0,c0+1},{r0+8,c0},{r0+8,c0+1}
__device__ __forceinline__ uint32_t addrP2(uint32_t base, int r0, int c0, int lane) {
    int grp = lane >> 3;
    return taddr(base, r0 + (grp >> 1) * 8 + (lane & 7), c0 + (grp & 1));
}

// ---------------- prepass: fp32 -> fp16, swizzled tile blobs (8 elems/thread) ----------------
__global__ void prep_kernel(const float* __restrict__ q, const float* __restrict__ k,
                            const float* __restrict__ v) {
    const int t = blockIdx.y;
    const float* src = (t == 0) ? q : (t == 1) ? k : v;
    const float sc = (t == 0) ? (0.125f * 1.44269504088896f) : 1.f;  // fold 1/8 and log2e into Q
    uint32_t i8 = blockIdx.x * blockDim.x + threadIdx.x;   // 16B-chunk index
    uint32_t c   = i8 & 7;                 // d-chunk (8 halves per chunk)
    uint32_t row = (i8 >> 3) & (Ln - 1);
    uint32_t b   = i8 >> 14;
    const float4* s4 = reinterpret_cast<const float4*>(src + ((size_t)(b * Ln + row)) * Dn + c * 8);
    float4 x0 = s4[0], x1 = s4[1];
    uint32_t h0 = pkh2(x0.x * sc, x0.y * sc);
    uint32_t h1 = pkh2(x0.z * sc, x0.w * sc);
    uint32_t h2 = pkh2(x1.x * sc, x1.y * sc);
    uint32_t h3 = pkh2(x1.z * sc, x1.w * sc);
    uint32_t tile = row >> 7, r = row & 127;
    uint32_t off = sw128(r * 128 + c * 16);
    uint4* dst = reinterpret_cast<uint4*>(
        reinterpret_cast<char*>(g_h[t] + (size_t)(b * NT + tile) * TILE_ELEMS) + off);
    *dst = make_uint4(h0, h1, h2, h3);
}

__device__ __forceinline__ void fetch_kv(uint32_t dst, int b, int j, int tid) {
    size_t blob = (size_t)(b * NT + j) * TILE_ELEMS;
    const char* kh = (const char*)(g_h[1] + blob);
    const char* vh = (const char*)(g_h[2] + blob);
    #pragma unroll
    for (int i = tid; i < TILE_BYTES / 16; i += NTH) {
        uint32_t o = (uint32_t)i * 16;
        CP16(dst + o, kh + o);
        CP16(dst + TILE_BYTES + o, vh + o);
    }
}

// tile-visit order: ii=0..15 -> j = t..15, 0..t-1 ; ii=16 -> j=t (bw diag pass)
__device__ __forceinline__ int seqj(int ii, int t) {
    return (ii < NT - t) ? (t + ii) : (ii - (NT - t));
}

// ---------------- main fused kernel ----------------
__global__ __launch_bounds__(NTH, 1)
void attn_hmma(float* __restrict__ O) {
    extern __shared__ char smem[];
    const uint32_t sb = smem_u32(smem);
    const int tid = threadIdx.x, lane = tid & 31, w = tid >> 5;
    const int b = blockIdx.y, t = blockIdx.x;
    const int wm = w >> 2, wn = w & 3;          // 4 m-warps x 4 n-warps
    const int g = lane >> 2, tig = lane & 3;
    const int m0 = wm * 32;            // warp's local row base (rows m0..m0+31)
    const int nb = wn * 32;            // warp's key base within tile
    const uint32_t ones2[2] = {0x3C003C00u, 0x3C003C00u};   // fp16 {1,1}

    // prologue: Q + KV(0), KV(1)
    {
        size_t qb = (size_t)(b * NT + t) * TILE_ELEMS;
        const char* qh = (const char*)(g_h[0] + qb);
        #pragma unroll
        for (int i = tid; i < TILE_BYTES / 16; i += NTH) {
            uint32_t o = (uint32_t)i * 16;
            CP16(sb + SM_QH + o, qh + o);
        }
        fetch_kv(sb + KVBUF(0), b, seqj(0, t), tid);
        CPCOMMIT();
        fetch_kv(sb + KVBUF(1), b, seqj(1, t), tid);
        CPCOMMIT();
    }

    float oacc[2][8][4];   // [h][d-frag][c]
    float lacc[2][4];      // row sums via ones-MMA
    #pragma unroll
    for (int h = 0; h < 2; h++) {
        #pragma unroll
        for (int n = 0; n < 8; n++)
            #pragma unroll
            for (int c = 0; c < 4; c++) oacc[h][n][c] = 0.f;
        #pragma unroll
        for (int c = 0; c < 4; c++) lacc[h][c] = 0.f;
    }

    #pragma unroll 1
    for (int ii = 0; ii <= NT; ii++) {
        // prefetch 2 ahead into 4-deep ring; ensure KV(ii) complete
        if (ii + 2 <= NT) {
            fetch_kv(sb + KVBUF((ii + 2) & 3), b, seqj(ii + 2, t), tid);
            CPCOMMIT();
            CPWAIT2();
        } else if (ii + 1 <= NT) {
            CPWAIT1();
        } else {
            CPWAIT0();
        }
        __syncthreads();                 // KV(ii) visible to all warps
        const uint32_t kb = sb + KVBUF(ii & 3);

        // ---- S(ii) = Q @ K^T : warp tile 32 rows x 32 keys ----
        float sacc[2][4][4];
        #pragma unroll
        for (int h = 0; h < 2; h++)
            #pragma unroll
            for (int n = 0; n < 4; n++)
                #pragma unroll
                for (int c = 0; c < 4; c++) sacc[h][n][c] = 0.f;

        #pragma unroll
        for (int kk = 0; kk < 4; kk++) {
            uint32_t qf0[4], qf1[4];
            ldsm4(qf0, addrP1(sb + SM_QH, m0, 2 * kk, lane));
            ldsm4(qf1, addrP1(sb + SM_QH, m0 + 16, 2 * kk, lane));
            uint32_t kf[2][4];
            ldsm4(kf[0], addrP2(kb, nb, 2 * kk, lane));
            ldsm4(kf[1], addrP2(kb, nb + 16, 2 * kk, lane));
            #pragma unroll
            for (int p = 0; p < 2; p++)
                #pragma unroll
                for (int s = 0; s < 2; s++) {
                    mma16816(sacc[0][p * 2 + s], qf0, &kf[p][s * 2]);
                    mma16816(sacc[1][p * 2 + s], qf1, &kf[p][s * 2]);
                }
        }

        // ---- mask + pack + f16x2 exp2 -> ph (A-frags of P) ----
        const int j = seqj(ii, t);
        const int mdir = (j == t) ? ((ii < NT - t) ? 1 : 2) : 0;   // 1=fw diag, 2=bw diag
        uint32_t ph[2][2][4];    // [h][k16-chunk][4 A-regs]
        #pragma unroll
        for (int h = 0; h < 2; h++) {
            const int lr = m0 + h * 16 + g;
            #pragma unroll
            for (int n = 0; n < 4; n++) {
                const int lc = nb + n * 8 + 2 * tig;
                float p0 = sacc[h][n][0], p1 = sacc[h][n][1];
                float p2 = sacc[h][n][2], p3 = sacc[h][n][3];
                if (mdir == 1) {        // fw: zero strictly-lower (col < row)
                    if (lc < lr)         p0 = -1e5f;
                    if (lc + 1 < lr)     p1 = -1e5f;
                    if (lc < lr + 8)     p2 = -1e5f;
                    if (lc + 1 < lr + 8) p3 = -1e5f;
                } else if (mdir == 2) { // bw: zero strictly-upper (col > row)
                    if (lc > lr)         p0 = -1e5f;
                    if (lc + 1 > lr)     p1 = -1e5f;
                    if (lc > lr + 8)     p2 = -1e5f;
                    if (lc + 1 > lr + 8) p3 = -1e5f;
                }
                ph[h][n >> 1][(n & 1) * 2 + 0] = ex2h2(pkh2(p0, p1));  // -1e5 -> -inf -> 0
                ph[h][n >> 1][(n & 1) * 2 + 1] = ex2h2(pkh2(p2, p3));
            }
        }

        // ---- O += P @ V, l += P @ 1 : contraction over this warp's 32 keys ----
        {
            const uint32_t vb = kb + TILE_BYTES;
            #pragma unroll
            for (int c = 0; c < 2; c++) {
                uint32_t vf[4][4];
                #pragma unroll
                for (int p = 0; p < 4; p++)
                    ldsm4t(vf[p], addrP1(vb, nb + c * 16, 2 * p, lane));
                #pragma unroll
                for (int h = 0; h < 2; h++) {
                    #pragma unroll
                    for (int p = 0; p < 4; p++)
                        #pragma unroll
                        for (int s = 0; s < 2; s++)
                            mma16816(oacc[h][p * 2 + s], ph[h][c], &vf[p][s * 2]);
                    mma16816(lacc[h], ph[h][c], ones2);
                }
            }
        }

        // ---- phase epilogue: 4-way cross-warp O reduction ----
        if (ii == NT - 1 - t || ii == NT) {
            const bool addmode = (ii == NT);
            float* lbuf = (float*)(smem + SM_LB);
            if (tig == 0) {
                #pragma unroll
                for (int h = 0; h < 2; h++) {
                    lbuf[wn * 128 + m0 + h * 16 + g]     = lacc[h][0];
                    lbuf[wn * 128 + m0 + h * 16 + g + 8] = lacc[h][2];
                }
            }
            // stage 1: wn1 -> region0, wn2 -> region1
            if (wn == 1 || wn == 2) {
                float* ob = (float*)(smem + SM_OB + (uint32_t)(wn - 1) * OREG);
                #pragma unroll
                for (int h = 0; h < 2; h++)
                    #pragma unroll
                    for (int n = 0; n < 8; n++) {
                        const int d = n * 8 + 2 * tig;
                        const int rr0 = m0 + h * 16 + g;
                        *(float2*)&ob[rr0 * OST + d]       = make_float2(oacc[h][n][0], oacc[h][n][1]);
                        *(float2*)&ob[(rr0 + 8) * OST + d] = make_float2(oacc[h][n][2], oacc[h][n][3]);
                    }
            }
            __syncthreads();
            // stage 2: wn3 folds itself into region0; wn0 folds region1 into its regs
            if (wn == 3) {
                float* ob = (float*)(smem + SM_OB);
                #pragma unroll
                for (int h = 0; h < 2; h++)
                    #pragma unroll
                    for (int n = 0; n < 8; n++) {
                        const int d = n * 8 + 2 * tig;
                        const int rr0 = m0 + h * 16 + g;
                        float2 e0 = *(float2*)&ob[rr0 * OST + d];
                        float2 e1 = *(float2*)&ob[(rr0 + 8) * OST + d];
                        *(float2*)&ob[rr0 * OST + d] =
                            make_float2(e0.x + oacc[h][n][0], e0.y + oacc[h][n][1]);
                        *(float2*)&ob[(rr0 + 8) * OST + d] =
                            make_float2(e1.x + oacc[h][n][2], e1.y + oacc[h][n][3]);
                    }
            } else if (wn == 0) {
                float* ob = (float*)(smem + SM_OB + OREG);
                #pragma unroll
                for (int h = 0; h < 2; h++)
                    #pragma unroll
                    for (int n = 0; n < 8; n++) {
                        const int d = n * 8 + 2 * tig;
                        const int rr0 = m0 + h * 16 + g;
                        float2 e0 = *(float2*)&ob[rr0 * OST + d];
                        float2 e1 = *(float2*)&ob[(rr0 + 8) * OST + d];
                        oacc[h][n][0] += e0.x; oacc[h][n][1] += e0.y;
                        oacc[h][n][2] += e1.x; oacc[h][n][3] += e1.y;
                    }
            }
            __syncthreads();
            // stage 3: wn0 adds region0 (wn1+wn3), normalizes, writes gmem
            if (wn == 0) {
                float* ob = (float*)(smem + SM_OB);
                #pragma unroll
                for (int h = 0; h < 2; h++) {
                    const int rr0 = m0 + h * 16 + g, rr1 = rr0 + 8;
                    const float inv0 = 1.f / (lbuf[rr0] + lbuf[128 + rr0] +
                                              lbuf[256 + rr0] + lbuf[384 + rr0]);
                    const float inv1 = 1.f / (lbuf[rr1] + lbuf[128 + rr1] +
                                              lbuf[256 + rr1] + lbuf[384 + rr1]);
                    #pragma unroll
                    for (int n = 0; n < 8; n++) {
                        const int d = n * 8 + 2 * tig;
                        float2 e0 = *(float2*)&ob[rr0 * OST + d];
                        float2 e1 = *(float2*)&ob[rr1 * OST + d];
                        float r0 = (oacc[h][n][0] + e0.x) * inv0;
                        float r1 = (oacc[h][n][1] + e0.y) * inv0;
                        float r2 = (oacc[h][n][2] + e1.x) * inv1;
                        float r3 = (oacc[h][n][3] + e1.y) * inv1;
                        float2* g0 = (float2*)(O + ((size_t)b * Ln + t * BT + rr0) * Dn + d);
                        float2* g1 = (float2*)(O + ((size_t)b * Ln + t * BT + rr1) * Dn + d);
                        if (addmode) {
                            float2 q0 = *g0, q1 = *g1;
                            *g0 = make_float2(q0.x + r0, q0.y + r1);
                            *g1 = make_float2(q1.x + r2, q1.y + r3);
                        } else {
                            *g0 = make_float2(r0, r1);
                            *g1 = make_float2(r2, r3);
                        }
                    }
                }
            }
            if (!addmode) {     // reset accumulators for the bw phase
                #pragma unroll
                for (int h = 0; h < 2; h++) {
                    #pragma unroll
                    for (int n = 0; n < 8; n++)
                        #pragma unroll
                        for (int c = 0; c < 4; c++) oacc[h][n][c] = 0.f;
                    #pragma unroll
                    for (int c = 0; c < 4; c++) lacc[h][c] = 0.f;
                }
            }
        }
    }
}

extern "C" void kernel_launch(void* const* d_in, const int* in_sizes, int n_in,
                              void* d_out, int out_size) {
    const float* q = (const float*)d_in[0];
    const float* k = (const float*)d_in[1];
    const float* v = (const float*)d_in[2];
    float* o = (float*)d_out;

    // 16B-chunks per tensor = Bn*Ln*Dn/8 = 131072 -> 512 blocks x 256 threads
    dim3 pg((Bn * Ln * Dn) / 8 / 256, 3);
    prep_kernel<<<pg, 256>>>(q, k, v);

    cudaFuncSetAttribute(attn_hmma,
                         cudaFuncAttributeMaxDynamicSharedMemorySize, SMEM_TOTAL);
    dim3 grid(NT, Bn);
    attn_hmma<<<grid, NTH, SMEM_TOTAL>>>(o);
}

// round 12
// speedup vs baseline: 1.4289x; 1.4289x over previous
#include <cuda_runtime.h>
#include <cuda_fp16.h>
#include <stdint.h>

#define Bn 8
#define Ln 2048
#define Dn 64
#define BT 128
#define NT 16
#define NTH 512
#define TILE_ELEMS (BT * Dn)          // 8192
#define TILE_BYTES (TILE_ELEMS * 2)   // 16384

// fp16 scratch: [0]=Q(prescaled by 0.125*log2e), [1]=K, [2]=V; SW128-swizzled tile blobs
__device__ __align__(256) __half g_h[3][Bn * Ln * Dn];

__host__ __device__ __forceinline__ uint32_t sw128(uint32_t x) {
    return x ^ ((x >> 3) & 0x70);
}

// ---------------- smem layout (bytes) ----------------
#define SM_QH 0
#define SM_KV TILE_BYTES                        // 4 ring bufs x {Kh, Vh} = 131072
#define KVBUF(i) (SM_KV + (uint32_t)(i) * 2u * TILE_BYTES)
#define SM_OBUF (SM_KV + 8 * TILE_BYTES)        // 147456: 128*64 floats = 32768 B
#define SM_LBUF (SM_OBUF + 32768)               // 180224: 2*128 floats
#define SMEM_TOTAL (SM_LBUF + 1024)             // 181248

// ---------------- asm helpers (base ISA, compute_103-safe) ----------------
__device__ __forceinline__ uint32_t smem_u32(const void* p) {
    uint32_t a;
    asm("{ .reg .u64 t; cvta.to.shared.u64 t, %1; cvt.u32.u64 %0, t; }" : "=r"(a) : "l"(p));
    return a;
}
#define CP16(dst, src) \
    asm volatile("cp.async.cg.shared.global [%0], [%1], 16;" :: "r"(dst), "l"(src))
#define CPCOMMIT() asm volatile("cp.async.commit_group;" ::: "memory")
#define CPWAIT2()  asm volatile("cp.async.wait_group 2;" ::: "memory")
#define CPWAIT1()  asm volatile("cp.async.wait_group 1;" ::: "memory")
#define CPWAIT0()  asm volatile("cp.async.wait_group 0;" ::: "memory")

__device__ __forceinline__ void ldsm4(uint32_t* r, uint32_t a) {
    asm volatile("ldmatrix.sync.aligned.m8n8.x4.shared.b16 {%0,%1,%2,%3}, [%4];"
                 : "=r"(r[0]), "=r"(r[1]), "=r"(r[2]), "=r"(r[3]) : "r"(a));
}
__device__ __forceinline__ void ldsm4t(uint32_t* r, uint32_t a) {
    asm volatile("ldmatrix.sync.aligned.m8n8.x4.trans.shared.b16 {%0,%1,%2,%3}, [%4];"
                 : "=r"(r[0]), "=r"(r[1]), "=r"(r[2]), "=r"(r[3]) : "r"(a));
}
__device__ __forceinline__ void mma16816(float* c, const uint32_t* a, const uint32_t* b) {
    asm volatile("mma.sync.aligned.m16n8k16.row.col.f32.f16.f16.f32 "
                 "{%0,%1,%2,%3}, {%4,%5,%6,%7}, {%8,%9}, {%0,%1,%2,%3};"
                 : "+f"(c[0]), "+f"(c[1]), "+f"(c[2]), "+f"(c[3])
                 : "r"(a[0]), "r"(a[1]), "r"(a[2]), "r"(a[3]), "r"(b[0]), "r"(b[1]));
}
// pack two fp32 to half2 (bits), then exp2 on both halves in one MUFU op
__device__ __forceinline__ uint32_t pkh2(float lo, float hi) {
    __half2 h = __floats2half2_rn(lo, hi);
    return *reinterpret_cast<uint32_t*>(&h);
}
__device__ __forceinline__ uint32_t ex2h2(uint32_t x) {
    uint32_t r;
    asm("ex2.approx.f16x2 %0, %1;" : "=r"(r) : "r"(x));
    return r;
}

// swizzled address of (row, 16B-chunk) in a 128x64 fp16 tile blob
__device__ __forceinline__ uint32_t taddr(uint32_t base, int row, int ch) {
    return base + ((uint32_t)row << 7) + (uint32_t)((ch ^ (row & 7)) << 4);
}
// pattern P1 (A-frag / V trans-frag): groups {r0,c0},{r0+8,c0},{r0,c0+1},{r0+8,c0+1}
__device__ __forceinline__ uint32_t addrP1(uint32_t base, int r0, int c0, int lane) {
    int grp = lane >> 3;
    return taddr(base, r0 + (grp & 1) * 8 + (lane & 7), c0 + (grp >> 1));
}
// pattern P2 (K B-frag): groups {r0,c0},{r0,c0+1},{r0+8,c0},{r0+8,c0+1}
__device__ __forceinline__ uint32_t addrP2(uint32_t base, int r0, int c0, int lane) {
    int grp = lane >> 3;
    return taddr(base, r0 + (grp >> 1) * 8 + (lane & 7), c0 + (grp & 1));
}

// ---------------- prepass: fp32 -> fp16, swizzled tile blobs (8 elems/thread) ----------------
__global__ void prep_kernel(const float* __restrict__ q, const float* __restrict__ k,
                            const float* __restrict__ v) {
    const int t = blockIdx.y;
    const float* src = (t == 0) ? q : (t == 1) ? k : v;
    const float sc = (t == 0) ? (0.125f * 1.44269504088896f) : 1.f;  // fold 1/8 and log2e into Q
    uint32_t i8 = blockIdx.x * blockDim.x + threadIdx.x;   // 16B-chunk index
    uint32_t c   = i8 & 7;                 // d-chunk (8 halves per chunk)
    uint32_t row = (i8 >> 3) & (Ln - 1);
    uint32_t b   = i8 >> 14;
    const float4* s4 = reinterpret_cast<const float4*>(src + ((size_t)(b * Ln + row)) * Dn + c * 8);
    float4 x0 = s4[0], x1 = s4[1];
    uint32_t h0 = pkh2(x0.x * sc, x0.y * sc);
    uint32_t h1 = pkh2(x0.z * sc, x0.w * sc);
    uint32_t h2 = pkh2(x1.x * sc, x1.y * sc);
    uint32_t h3 = pkh2(x1.z * sc, x1.w * sc);
    uint32_t tile = row >> 7, r = row & 127;
    uint32_t off = sw128(r * 128 + c * 16);
    uint4* dst = reinterpret_cast<uint4*>(
        reinterpret_cast<char*>(g_h[t] + (size_t)(b * NT + tile) * TILE_ELEMS) + off);
    *dst = make_uint4(h0, h1, h2, h3);
}

__device__ __forceinline__ void fetch_kv(uint32_t dst, int b, int j, int tid) {
    size_t blob = (size_t)(b * NT + j) * TILE_ELEMS;
    const char* kh = (const char*)(g_h[1] + blob);
    const char* vh = (const char*)(g_h[2] + blob);
    #pragma unroll
    for (int i = tid; i < TILE_BYTES / 16; i += NTH) {
        uint32_t o = (uint32_t)i * 16;
        CP16(dst + o, kh + o);
        CP16(dst + TILE_BYTES + o, vh + o);
    }
}

// tile-visit order: ii=0..15 -> j = t..15, 0..t-1 ; ii=16 -> j=t (bw diag pass)
__device__ __forceinline__ int seqj(int ii, int t) {
    return (ii < NT - t) ? (t + ii) : (ii - (NT - t));
}

// ---------------- main fused kernel ----------------
__global__ __launch_bounds__(NTH, 1)
void attn_hmma(float* __restrict__ O) {
    extern __shared__ char smem[];
    const uint32_t sb = smem_u32(smem);
    const int tid = threadIdx.x, lane = tid & 31, w = tid >> 5;
    const int b = blockIdx.y, t = blockIdx.x;
    const int wm = w >> 1, wn = w & 1;          // 8 m-warps x 2 n-warps
    const int g = lane >> 2, tig = lane & 3;
    const int m0 = wm * 16;            // warp's local row base (rows m0..m0+15)
    const int nb = wn * 64;            // warp's key base within tile
    const uint32_t ones2[2] = {0x3C003C00u, 0x3C003C00u};   // fp16 {1,1}

    // prologue: Q + KV(0) (group 0), KV(1) (group 1)
    {
        size_t qb = (size_t)(b * NT + t) * TILE_ELEMS;
        const char* qh = (const char*)(g_h[0] + qb);
        #pragma unroll
        for (int i = tid; i < TILE_BYTES / 16; i += NTH) {
            uint32_t o = (uint32_t)i * 16;
            CP16(sb + SM_QH + o, qh + o);
        }
        fetch_kv(sb + KVBUF(0), b, seqj(0, t), tid);
        CPCOMMIT();
        fetch_kv(sb + KVBUF(1), b, seqj(1, t), tid);
        CPCOMMIT();
    }

    float oacc[8][4];
    float lacc[4];
    #pragma unroll
    for (int n = 0; n < 8; n++)
        #pragma unroll
        for (int c = 0; c < 4; c++) oacc[n][c] = 0.f;
    #pragma unroll
    for (int c = 0; c < 4; c++) lacc[c] = 0.f;

    uint32_t qf[4][4];       // Q fragments, resident across all tiles (16 regs)

    #pragma unroll 1
    for (int ii = 0; ii <= NT; ii++) {
        // prefetch 2 ahead into 4-deep ring; ensure KV(ii) complete
        if (ii + 2 <= NT) {
            fetch_kv(sb + KVBUF((ii + 2) & 3), b, seqj(ii + 2, t), tid);
            CPCOMMIT();
            CPWAIT2();
        } else if (ii + 1 <= NT) {
            CPWAIT1();
        } else {
            CPWAIT0();
        }
        __syncthreads();                 // KV(ii) visible; buf[(ii+2)&3] free for writers
        const uint32_t kb = sb + KVBUF(ii & 3);

        if (ii == 0) {                   // hoist Q fragments once (Q was in group 0)
            #pragma unroll
            for (int kk = 0; kk < 4; kk++)
                ldsm4(qf[kk], addrP1(sb + SM_QH, m0, 2 * kk, lane));
        }

        const int j = seqj(ii, t);
        const int mdir = (j == t) ? ((ii < NT - t) ? 1 : 2) : 0;   // 1=fw diag, 2=bw diag
        const int lr = m0 + g;

        // ---- per key-16 group: S = Q @ K^T, then fused mask+exp -> ph[p] ----
        uint32_t ph[4][4];               // A-frags of P (16 regs)
        #pragma unroll
        for (int p = 0; p < 4; p++) {
            float s0[4] = {0.f, 0.f, 0.f, 0.f};
            float s1[4] = {0.f, 0.f, 0.f, 0.f};
            #pragma unroll
            for (int kk = 0; kk < 4; kk++) {
                uint32_t kf[4];
                ldsm4(kf, addrP2(kb, nb + p * 16, 2 * kk, lane));
                mma16816(s0, qf[kk], &kf[0]);
                mma16816(s1, qf[kk], &kf[2]);
            }
            const int lc0 = nb + p * 16 + 2 * tig;   // frag0 cols; frag1 = +8
            if (mdir == 1) {            // fw: zero strictly-lower (col < row)
                if (lc0 < lr)          s0[0] = -1e5f;
                if (lc0 + 1 < lr)      s0[1] = -1e5f;
                if (lc0 < lr + 8)      s0[2] = -1e5f;
                if (lc0 + 1 < lr + 8)  s0[3] = -1e5f;
                if (lc0 + 8 < lr)      s1[0] = -1e5f;
                if (lc0 + 9 < lr)      s1[1] = -1e5f;
                if (lc0 + 8 < lr + 8)  s1[2] = -1e5f;
                if (lc0 + 9 < lr + 8)  s1[3] = -1e5f;
            } else if (mdir == 2) {     // bw: zero strictly-upper (col > row)
                if (lc0 > lr)          s0[0] = -1e5f;
                if (lc0 + 1 > lr)      s0[1] = -1e5f;
                if (lc0 > lr + 8)      s0[2] = -1e5f;
                if (lc0 + 1 > lr + 8)  s0[3] = -1e5f;
                if (lc0 + 8 > lr)      s1[0] = -1e5f;
                if (lc0 + 9 > lr)      s1[1] = -1e5f;
                if (lc0 + 8 > lr + 8)  s1[2] = -1e5f;
                if (lc0 + 9 > lr + 8)  s1[3] = -1e5f;
            }
            ph[p][0] = ex2h2(pkh2(s0[0], s0[1]));   // -1e5 -> fp16 -inf -> 0
            ph[p][1] = ex2h2(pkh2(s0[2], s0[3]));
            ph[p][2] = ex2h2(pkh2(s1[0], s1[1]));
            ph[p][3] = ex2h2(pkh2(s1[2], s1[3]));
        }

        // ---- O += P @ V, l += P @ 1 (contraction over this warp's 64 keys) ----
        {
            const uint32_t vb = kb + TILE_BYTES;
            #pragma unroll
            for (int k2 = 0; k2 < 4; k2++) {
                uint32_t vf[4][4];
                #pragma unroll
                for (int p = 0; p < 4; p++)
                    ldsm4t(vf[p], addrP1(vb, nb + k2 * 16, 2 * p, lane));
                #pragma unroll
                for (int p = 0; p < 4; p++)
                    #pragma unroll
                    for (int s = 0; s < 2; s++)
                        mma16816(oacc[p * 2 + s], ph[k2], &vf[p][s * 2]);
                mma16816(lacc, ph[k2], ones2);   // row sums
            }
        }

        // ---- phase epilogue ----
        if (ii == NT - 1 - t || ii == NT) {
            const bool addmode = (ii == NT);
            float* lbuf = (float*)(smem + SM_LBUF);
            if (tig == 0) {
                lbuf[wn * 128 + m0 + g] = lacc[0];
                lbuf[wn * 128 + m0 + g + 8] = lacc[2];
            }
            float* obuf = (float*)(smem + SM_OBUF);
            __syncthreads();
            if (wn == 1) {      // n-half 1 dumps its partial O
                #pragma unroll
                for (int n = 0; n < 8; n++) {
                    const int d = n * 8 + 2 * tig;
                    *(float2*)&obuf[(m0 + g) * 64 + d]     = make_float2(oacc[n][0], oacc[n][1]);
                    *(float2*)&obuf[(m0 + g + 8) * 64 + d] = make_float2(oacc[n][2], oacc[n][3]);
                }
            }
            __syncthreads();
            if (wn == 0) {      // n-half 0 combines, normalizes, writes gmem
                const int rr0 = m0 + g, rr1 = rr0 + 8;
                const float inv0 = 1.f / (lbuf[rr0] + lbuf[128 + rr0]);
                const float inv1 = 1.f / (lbuf[rr1] + lbuf[128 + rr1]);
                #pragma unroll
                for (int n = 0; n < 8; n++) {
                    const int d = n * 8 + 2 * tig;
                    float2 e0 = *(float2*)&obuf[rr0 * 64 + d];
                    float2 e1 = *(float2*)&obuf[rr1 * 64 + d];
                    float r0 = (oacc[n][0] + e0.x) * inv0;
                    float r1 = (oacc[n][1] + e0.y) * inv0;
                    float r2 = (oacc[n][2] + e1.x) * inv1;
                    float r3 = (oacc[n][3] + e1.y) * inv1;
                    float2* g0 = (float2*)(O + ((size_t)b * Ln + t * BT + rr0) * Dn + d);
                    float2* g1 = (float2*)(O + ((size_t)b * Ln + t * BT + rr1) * Dn + d);
                    if (addmode) {
                        float2 q0 = *g0, q1 = *g1;
                        *g0 = make_float2(q0.x + r0, q0.y + r1);
                        *g1 = make_float2(q1.x + r2, q1.y + r3);
                    } else {
                        *g0 = make_float2(r0, r1);
                        *g1 = make_float2(r2, r3);
                    }
                }
            }
            if (!addmode) {     // reset accumulators for the bw phase
                #pragma unroll
                for (int n = 0; n < 8; n++)
                    #pragma unroll
                    for (int c = 0; c < 4; c++) oacc[n][c] = 0.f;
                #pragma unroll
                for (int c = 0; c < 4; c++) lacc[c] = 0.f;
            }
        }
    }
}

extern "C" void kernel_launch(void* const* d_in, const int* in_sizes, int n_in,
                              void* d_out, int out_size) {
    const float* q = (const float*)d_in[0];
    const float* k = (const float*)d_in[1];
    const float* v = (const float*)d_in[2];
    float* o = (float*)d_out;

    // 16B-chunks per tensor = Bn*Ln*Dn/8 = 131072 -> 512 blocks x 256 threads
    dim3 pg((Bn * Ln * Dn) / 8 / 256, 3);
    prep_kernel<<<pg, 256>>>(q, k, v);

    cudaFuncSetAttribute(attn_hmma,
                         cudaFuncAttributeMaxDynamicSharedMemorySize, SMEM_TOTAL);
    dim3 grid(NT, Bn);
    attn_hmma<<<grid, NTH, SMEM_TOTAL>>>(o);
}